// round 15
// baseline (speedup 1.0000x reference)
#include <cuda_runtime.h>
#include <cstdint>

// ---------------- Problem constants (fixed by reference setup) ----------------
#define Zl      384
#define MBg     46
#define DEGc    7
#define Bb      128                  // batch
#define N_IN    25344                // transmitted bits
#define NLD     26112                // variable nodes (= N_IN + 2*Z)
#define M_CN    17664                // check nodes
#define E_TOT   (MBg * DEGc * Zl)    // 123648 edges
#define K_OUT   8448                 // info bits output per batch row
#define NITER   20
#define LLRMAX  20.0f

// ---------------- Device-global scratch (no runtime allocation) ----------------
__device__ float g_lch[NLD * Bb];    // -clipped channel LLR, batch-major [v*B+b]
__device__ float g_vn [NLD * Bb];    // VN totals (x_tot at the end)
__device__ float g_msg[E_TOT * Bb];  // explicit CN->VN messages, [e*B+b]
__device__ int   g_deg[NLD];         // VN degrees
__device__ int   g_cur[NLD];         // fill cursors
__device__ int   g_off[NLD + 1];     // CSR offsets
__device__ int   g_adj[E_TOT];       // edge ids per VN, sorted ascending

// ---------------- Init: zero counters + punctured lch region ----------------
__global__ void k_init() {
    const int i = blockIdx.x * blockDim.x + threadIdx.x;   // grid covers 2*Zl*Bb
    if (i < NLD) { g_deg[i] = 0; g_cur[i] = 0; }
    if (i < 2 * Zl * Bb) g_lch[i] = 0.0f;
}

// ---------------- Zero the message buffer (m_cv0 = 0) ----------------
__global__ void __launch_bounds__(256) k_zero_msg() {
    const int i = blockIdx.x * 256 + threadIdx.x;          // grid = E_TOT*Bb/4
    reinterpret_cast<float4*>(g_msg)[i] = make_float4(0.f, 0.f, 0.f, 0.f);
}

// ---------------- Prep: transpose + clip + negate channel LLRs ----------------
// lch[(2Z+n)*B + b] = -clip(llr[b*N_IN + n])
__global__ void __launch_bounds__(1024) k_prep(const float* __restrict__ llr) {
    __shared__ float sm[32][33];
    const int n0 = blockIdx.x * 32;
    const int b0 = blockIdx.y * 32;
    const int tx = threadIdx.x, ty = threadIdx.y;

    float v = llr[(b0 + ty) * N_IN + (n0 + tx)];
    v = fminf(fmaxf(v, -LLRMAX), LLRMAX);
    sm[ty][tx] = -v;
    __syncthreads();

    const int vv = 2 * Zl + n0 + ty;
    g_lch[vv * Bb + (b0 + tx)] = sm[tx][ty];
}

// ---------------- CSR build: count / scan / fill / sort ----------------
__global__ void __launch_bounds__(256) k_count(const int* __restrict__ col) {
    const int e = blockIdx.x * 256 + threadIdx.x;          // grid = E_TOT/256 exact
    atomicAdd(&g_deg[col[e]], 1);
}

__global__ void __launch_bounds__(1024) k_scan() {
    __shared__ int part[1024];
    const int t = threadIdx.x;
    const int base = t * 26;                               // 1024*26 = 26624 >= NLD
    int loc[26];
    int s = 0;
#pragma unroll
    for (int j = 0; j < 26; j++) {
        const int v = base + j;
        loc[j] = (v < NLD) ? g_deg[v] : 0;
        s += loc[j];
    }
    part[t] = s;
    __syncthreads();
    for (int ofs = 1; ofs < 1024; ofs <<= 1) {             // Hillis-Steele inclusive
        int add = (t >= ofs) ? part[t - ofs] : 0;
        __syncthreads();
        part[t] += add;
        __syncthreads();
    }
    int run = (t > 0) ? part[t - 1] : 0;                   // exclusive prefix
#pragma unroll
    for (int j = 0; j < 26; j++) {
        const int v = base + j;
        if (v < NLD) { g_off[v] = run; run += loc[j]; }
    }
    if (t == 1023) g_off[NLD] = run;                       // == E_TOT
}

__global__ void __launch_bounds__(256) k_fill(const int* __restrict__ col) {
    const int e = blockIdx.x * 256 + threadIdx.x;
    const int c = col[e];
    const int pos = atomicAdd(&g_cur[c], 1);
    g_adj[g_off[c] + pos] = e;
}

__global__ void __launch_bounds__(256) k_sort() {
    const int v = blockIdx.x * 256 + threadIdx.x;
    if (v >= NLD) return;
    const int o = g_off[v];
    const int n = g_off[v + 1] - o;
    for (int a = 1; a < n; a++) {                          // ascending edge ids
        const int key = g_adj[o + a];
        int q = a - 1;
        while (q >= 0 && g_adj[o + q] > key) { g_adj[o + q + 1] = g_adj[o + q]; q--; }
        g_adj[o + q + 1] = key;
    }
}

// ---------------- VN gather: vn = scatter-add INTO lch, ascending edge order --
// Models XLA's algebraic-simplifier fold  add(lch, scatter(zeros,col,m)) ->
// scatter(lch, col, m)  executed by the CPU emitter sequentially in ascending
// update (edge-id) order:  vn = (((lch + m_e1) + m_e2) + ...)  bit-exact.
__global__ void __launch_bounds__(128) k_vn() {
    const int v = blockIdx.x;                              // grid = NLD
    const int b = threadIdx.x;                             // 128 batch lanes
    const int o  = g_off[v];
    const int dg = g_off[v + 1] - o;
    float S = __ldg(&g_lch[v * Bb + b]);                   // lch seeds accumulator
    for (int j = 0; j < dg; j++) {
        const int e = __ldg(&g_adj[o + j]);                // warp-uniform
        S += __ldg(&g_msg[e * Bb + b]);                    // coalesced in b
    }
    g_vn[v * Bb + b] = S;
}

// ---------------- CN update: min-sum, write messages in place ----------------
// One thread per (check node m, batch b). No atomics: each edge has one owner.
__global__ void __launch_bounds__(256) k_cn(const int* __restrict__ col) {
    const int tid = blockIdx.x * 256 + threadIdx.x;        // grid = M_CN*Bb/256
    const int b = tid & (Bb - 1);
    const int m = tid >> 7;
    const int r = m / Zl;
    const int i = m - r * Zl;
    const int ebase = r * (DEGc * Zl) + i;                 // edge e_d = ebase + d*Z

    float min1 = 1e30f, min2 = 1e30f;
    int   idx = 0;
    unsigned int sgnbits = 0, par = 0;

#pragma unroll
    for (int d = 0; d < DEGc; d++) {
        const int e = ebase + d * Zl;
        const int c = __ldg(&col[e]);                      // warp-uniform
        // m_vc = vn_sum[col] - m_cv  (bit-exact: vn from gather, msg explicit)
        const float tv = __ldg(&g_vn[c * Bb + b]) - g_msg[e * Bb + b];
        const float mag = fabsf(tv);
        const unsigned int neg = (tv < 0.0f) ? 1u : 0u;
        sgnbits |= neg << d;
        par ^= neg;
        // first-argmin tie-break via strict < over ascending d (== ref eid order)
        if (mag < min1) { min2 = min1; min1 = mag; idx = d; }
        else if (mag < min2) { min2 = mag; }
    }

#pragma unroll
    for (int d = 0; d < DEGc; d++) {
        const float mo = (d == idx) ? min2 : min1;
        const unsigned int s = ((sgnbits >> d) ^ par) & 1u;  // sign_tot * sign_e
        g_msg[(ebase + d * Zl) * Bb + b] = s ? -mo : mo;     // exact copy/negate
    }
}

// ---------------- Output: negate + transpose, first K info bits ----------------
__global__ void __launch_bounds__(1024) k_out(float* __restrict__ out) {
    __shared__ float sm[32][33];
    const int v0 = blockIdx.x * 32;
    const int b0 = blockIdx.y * 32;
    const int tx = threadIdx.x, ty = threadIdx.y;

    sm[ty][tx] = g_vn[(v0 + ty) * Bb + (b0 + tx)];         // coalesced in b
    __syncthreads();
    out[(b0 + ty) * K_OUT + (v0 + tx)] = -sm[tx][ty];      // coalesced in v
}

// ---------------- Host launcher (graph-capturable, no allocation) ----------------
extern "C" void kernel_launch(void* const* d_in, const int* in_sizes, int n_in,
                              void* d_out, int out_size) {
    const float* llr = (const float*)d_in[0];
    const int*   col = (const int*)d_in[2];
    float*       out = (float*)d_out;
    (void)in_sizes; (void)n_in; (void)out_size;

    // ---- per-launch deterministic prep ----
    k_init<<<(2 * Zl * Bb + 255) / 256, 256>>>();          // 384 blocks
    k_prep<<<dim3(N_IN / 32, Bb / 32), dim3(32, 32)>>>(llr);
    k_zero_msg<<<(E_TOT * Bb / 4) / 256, 256>>>();         // 15456 blocks
    k_count<<<E_TOT / 256, 256>>>(col);                    // 483 blocks (exact)
    k_scan<<<1, 1024>>>();
    k_fill<<<E_TOT / 256, 256>>>(col);
    k_sort<<<(NLD + 255) / 256, 256>>>();

    // ---- 20 flooding iterations: VN gather then CN update ----
    for (int t = 0; t < NITER; t++) {
        k_vn<<<NLD, 128>>>();
        k_cn<<<(M_CN * Bb) / 256, 256>>>(col);
    }
    // final x_tot = scatter-add of final messages into lch (same order)
    k_vn<<<NLD, 128>>>();
    k_out<<<dim3(K_OUT / 32, Bb / 32), dim3(32, 32)>>>(out);
}

// round 16
// speedup vs baseline: 1.3263x; 1.3263x over previous
#include <cuda_runtime.h>
#include <cstdint>

// ---------------- Problem constants (fixed by reference setup) ----------------
#define Zl      384
#define MBg     46
#define DEGc    7
#define Bb      128                  // batch
#define Bh      64                   // batch in float2 lanes
#define N_IN    25344                // transmitted bits
#define NLD     26112                // variable nodes (= N_IN + 2*Z)
#define M_CN    17664                // check nodes
#define E_TOT   (MBg * DEGc * Zl)    // 123648 edges
#define K_OUT   8448                 // info bits output per batch row
#define NITER   20
#define LLRMAX  20.0f
#define PADD    16                   // padded VN adjacency slots

// ---------------- Device-global scratch (no runtime allocation) ----------------
__device__ float g_lch [NLD * Bb];        // -clipped channel LLR, [v*B+b]
__device__ float g_vn  [NLD * Bb];        // VN totals (x_tot at the end)
__device__ float g_msg [(E_TOT + 1) * Bb];// messages + one always-zero dummy row
__device__ int   g_deg [NLD];             // VN degrees
__device__ int   g_cur [NLD];             // fill cursors
__device__ int   g_off [NLD + 1];         // CSR offsets
__device__ int   g_adj [E_TOT];           // edge ids per VN, sorted ascending
__device__ int   g_adj16[NLD * PADD];     // padded adjacency (dummy = E_TOT)

// ---------------- Init: zero counters + punctured lch region ----------------
__global__ void k_init() {
    const int i = blockIdx.x * blockDim.x + threadIdx.x;   // grid covers 2*Zl*Bb
    if (i < NLD) { g_deg[i] = 0; g_cur[i] = 0; }
    if (i < 2 * Zl * Bb) g_lch[i] = 0.0f;
}

// ---------------- Zero message buffer incl. dummy row (m_cv0 = 0) ----------------
__global__ void __launch_bounds__(256) k_zero_msg() {
    const int i = blockIdx.x * 256 + threadIdx.x;
    if (i < (E_TOT + 1) * Bb / 4)
        reinterpret_cast<float4*>(g_msg)[i] = make_float4(0.f, 0.f, 0.f, 0.f);
}

// ---------------- Prep: transpose + clip + negate channel LLRs ----------------
__global__ void __launch_bounds__(1024) k_prep(const float* __restrict__ llr) {
    __shared__ float sm[32][33];
    const int n0 = blockIdx.x * 32;
    const int b0 = blockIdx.y * 32;
    const int tx = threadIdx.x, ty = threadIdx.y;

    float v = llr[(b0 + ty) * N_IN + (n0 + tx)];
    v = fminf(fmaxf(v, -LLRMAX), LLRMAX);
    sm[ty][tx] = -v;
    __syncthreads();

    const int vv = 2 * Zl + n0 + ty;
    g_lch[vv * Bb + (b0 + tx)] = sm[tx][ty];
}

// ---------------- CSR build: count / scan / fill / sort / pad ----------------
__global__ void __launch_bounds__(256) k_count(const int* __restrict__ col) {
    const int e = blockIdx.x * 256 + threadIdx.x;          // grid exact
    atomicAdd(&g_deg[col[e]], 1);
}

__global__ void __launch_bounds__(1024) k_scan() {
    __shared__ int part[1024];
    const int t = threadIdx.x;
    const int base = t * 26;                               // 1024*26 >= NLD
    int loc[26];
    int s = 0;
#pragma unroll
    for (int j = 0; j < 26; j++) {
        const int v = base + j;
        loc[j] = (v < NLD) ? g_deg[v] : 0;
        s += loc[j];
    }
    part[t] = s;
    __syncthreads();
    for (int ofs = 1; ofs < 1024; ofs <<= 1) {             // Hillis-Steele inclusive
        int add = (t >= ofs) ? part[t - ofs] : 0;
        __syncthreads();
        part[t] += add;
        __syncthreads();
    }
    int run = (t > 0) ? part[t - 1] : 0;                   // exclusive prefix
#pragma unroll
    for (int j = 0; j < 26; j++) {
        const int v = base + j;
        if (v < NLD) { g_off[v] = run; run += loc[j]; }
    }
    if (t == 1023) g_off[NLD] = run;                       // == E_TOT
}

__global__ void __launch_bounds__(256) k_fill(const int* __restrict__ col) {
    const int e = blockIdx.x * 256 + threadIdx.x;
    const int c = col[e];
    const int pos = atomicAdd(&g_cur[c], 1);
    g_adj[g_off[c] + pos] = e;
}

// sort each VN's edges ascending, then emit padded table (dummy = E_TOT)
__global__ void __launch_bounds__(256) k_sort_pad() {
    const int v = blockIdx.x * 256 + threadIdx.x;
    if (v >= NLD) return;
    const int o = g_off[v];
    const int n = g_off[v + 1] - o;
    for (int a = 1; a < n; a++) {
        const int key = g_adj[o + a];
        int q = a - 1;
        while (q >= 0 && g_adj[o + q] > key) { g_adj[o + q + 1] = g_adj[o + q]; q--; }
        g_adj[o + q + 1] = key;
    }
#pragma unroll
    for (int j = 0; j < PADD; j++)
        g_adj16[v * PADD + j] = (j < n) ? g_adj[o + j] : E_TOT;
}

// ---------------- VN gather: vn = (((lch + m_e1) + m_e2) + ... ) ----------------
// Exactly reproduces XLA-CPU's lch-seeded sequential scatter order (ascending
// edge ids). Dummy slots append +0.0f AFTER all real edges -> value-exact
// (only possible -0.0 -> +0.0 flips, invisible downstream). Fixed 16-way unroll
// gives MLP=16; rare deg>16 handled by an in-order CSR tail.
__global__ void __launch_bounds__(256) k_vn(int nvn) {
    const int t  = blockIdx.x * 256 + threadIdx.x;         // grid = nvn*Bh/256
    const int b2 = t & (Bh - 1);
    const int v  = t >> 6;
    const float2* __restrict__ msg2 = reinterpret_cast<const float2*>(g_msg);

    int e[PADD];
#pragma unroll
    for (int j = 0; j < PADD; j += 4) {
        const int4 q = *reinterpret_cast<const int4*>(&g_adj16[v * PADD + j]); // warp-uniform
        e[j] = q.x; e[j + 1] = q.y; e[j + 2] = q.z; e[j + 3] = q.w;
    }

    float2 m[PADD];
#pragma unroll
    for (int j = 0; j < PADD; j++)
        m[j] = __ldg(&msg2[e[j] * Bh + b2]);               // coalesced; MLP=16

    const float2 l = __ldg(&reinterpret_cast<const float2*>(g_lch)[v * Bh + b2]);
    float Sx = l.x, Sy = l.y;
#pragma unroll
    for (int j = 0; j < PADD; j++) { Sx += m[j].x; Sy += m[j].y; }

    const int dg = g_deg[v];                               // exact tail, in order
    if (dg > PADD) {
        const int o = g_off[v];
        for (int j = PADD; j < dg; j++) {
            const float2 mm = __ldg(&msg2[g_adj[o + j] * Bh + b2]);
            Sx += mm.x; Sy += mm.y;
        }
    }
    reinterpret_cast<float2*>(g_vn)[v * Bh + b2] = make_float2(Sx, Sy);
}

// ---------------- CN update: min-sum, write messages in place ----------------
// One thread per (check node m, 2 batch lanes). No atomics: one owner per edge.
__global__ void __launch_bounds__(256) k_cn(const int* __restrict__ col) {
    const int t  = blockIdx.x * 256 + threadIdx.x;         // grid = M_CN*Bh/256
    const int b2 = t & (Bh - 1);
    const int m  = t >> 6;
    const int r  = m / Zl;
    const int i  = m - r * Zl;
    const int ebase = r * (DEGc * Zl) + i;                 // edge e_d = ebase + d*Z

    float2* __restrict__ msg2 = reinterpret_cast<float2*>(g_msg);
    const float2* __restrict__ vn2 = reinterpret_cast<const float2*>(g_vn);

    float min1x = 1e30f, min2x = 1e30f, min1y = 1e30f, min2y = 1e30f;
    int   idxx = 0, idxy = 0;
    unsigned int sgx = 0, px = 0, sgy = 0, py = 0;

#pragma unroll
    for (int d = 0; d < DEGc; d++) {
        const int e = ebase + d * Zl;
        const int c = __ldg(&col[e]);                      // warp-uniform
        const float2 vn = __ldg(&vn2[c * Bh + b2]);
        const float2 mo = msg2[e * Bh + b2];
        // m_vc = vn_sum[col] - m_cv  (bit-exact)
        const float tx = vn.x - mo.x;
        const float ty = vn.y - mo.y;
        const float ax = fabsf(tx), ay = fabsf(ty);
        const unsigned int nx = (tx < 0.0f) ? 1u : 0u;
        const unsigned int ny = (ty < 0.0f) ? 1u : 0u;
        sgx |= nx << d; px ^= nx;
        sgy |= ny << d; py ^= ny;
        // first-argmin tie-break via strict < over ascending d (== ref eid order)
        if (ax < min1x) { min2x = min1x; min1x = ax; idxx = d; }
        else if (ax < min2x) { min2x = ax; }
        if (ay < min1y) { min2y = min1y; min1y = ay; idxy = d; }
        else if (ay < min2y) { min2y = ay; }
    }

#pragma unroll
    for (int d = 0; d < DEGc; d++) {
        const float ox = (d == idxx) ? min2x : min1x;
        const float oy = (d == idxy) ? min2y : min1y;
        const unsigned int sx = ((sgx >> d) ^ px) & 1u;    // sign_tot * sign_e
        const unsigned int sy = ((sgy >> d) ^ py) & 1u;
        msg2[(ebase + d * Zl) * Bh + b2] =
            make_float2(sx ? -ox : ox, sy ? -oy : oy);     // exact copy/negate
    }
}

// ---------------- Output: negate + transpose, first K info bits ----------------
__global__ void __launch_bounds__(1024) k_out(float* __restrict__ out) {
    __shared__ float sm[32][33];
    const int v0 = blockIdx.x * 32;
    const int b0 = blockIdx.y * 32;
    const int tx = threadIdx.x, ty = threadIdx.y;

    sm[ty][tx] = g_vn[(v0 + ty) * Bb + (b0 + tx)];         // coalesced in b
    __syncthreads();
    out[(b0 + ty) * K_OUT + (v0 + tx)] = -sm[tx][ty];      // coalesced in v
}

// ---------------- Host launcher (graph-capturable, no allocation) ----------------
extern "C" void kernel_launch(void* const* d_in, const int* in_sizes, int n_in,
                              void* d_out, int out_size) {
    const float* llr = (const float*)d_in[0];
    const int*   col = (const int*)d_in[2];
    float*       out = (float*)d_out;
    (void)in_sizes; (void)n_in; (void)out_size;

    // ---- per-launch deterministic prep ----
    k_init<<<(2 * Zl * Bb + 255) / 256, 256>>>();          // 384 blocks
    k_prep<<<dim3(N_IN / 32, Bb / 32), dim3(32, 32)>>>(llr);
    k_zero_msg<<<((E_TOT + 1) * Bb / 4 + 255) / 256, 256>>>();
    k_count<<<E_TOT / 256, 256>>>(col);                    // 483 blocks (exact)
    k_scan<<<1, 1024>>>();
    k_fill<<<E_TOT / 256, 256>>>(col);
    k_sort_pad<<<(NLD + 255) / 256, 256>>>();

    // ---- 20 flooding iterations: VN gather then CN update ----
    const int vn_blocks = (NLD * Bh) / 256;                // 6528, exact
    const int cn_blocks = (M_CN * Bh) / 256;               // 4416, exact
    for (int t = 0; t < NITER; t++) {
        k_vn<<<vn_blocks, 256>>>(NLD);
        k_cn<<<cn_blocks, 256>>>(col);
    }
    // final x_tot: only the K_OUT info VNs are emitted
    k_vn<<<(K_OUT * Bh) / 256, 256>>>(K_OUT);              // 2112 blocks
    k_out<<<dim3(K_OUT / 32, Bb / 32), dim3(32, 32)>>>(out);
}